// round 9
// baseline (speedup 1.0000x reference)
#include <cuda_runtime.h>
#include <cuda_bf16.h>
#include <math.h>

#define BATCH 128
#define TLEN  2048
#define CH    128
#define EDIM  32
#define HDIM  64
#define PRED  336

typedef unsigned long long ull;

// scratch (allocation-free rule: __device__ globals)
__device__ __align__(16) float g_v[BATCH * EDIM];          // encoder output v
__device__ __align__(16) float g_U[PRED * BATCH * HDIM];   // running u-sums, 11 MB
__device__ __align__(16) float g_Mh[HDIM * HDIM];          // (Wo*Wh)^T rows
__device__ __align__(16) float g_Mg[HDIM * HDIM];
__device__ __align__(16) float g_ch[HDIM];
__device__ __align__(16) float g_cg[HDIM];
__device__ __align__(16) float g_Q [HDIM * CH];            // Wo*Wr
__device__ __align__(16) float g_cvec[CH];                 // bdo*Wr

// ---- packed f32x2 helpers (Blackwell) --------------------------------------
__device__ __forceinline__ ull fma2v(ull a, ull b, ull c) {
    ull d; asm("fma.rn.f32x2 %0, %1, %2, %3;" : "=l"(d) : "l"(a), "l"(b), "l"(c));
    return d;
}
__device__ __forceinline__ ull addx2(ull a, ull b) {
    ull d; asm("add.rn.f32x2 %0, %1, %2;" : "=l"(d) : "l"(a), "l"(b));
    return d;
}
__device__ __forceinline__ float2 unpk(ull v) {
    float2 r; asm("mov.b64 {%0, %1}, %2;" : "=f"(r.x), "=f"(r.y) : "l"(v));
    return r;
}
__device__ __forceinline__ ull pk(float lo, float hi) {
    ull v; asm("mov.b64 %0, {%1, %2};" : "=l"(v) : "f"(lo), "f"(hi));
    return v;
}
__device__ __forceinline__ ull pk1(float v) {
    ull r; asm("mov.b64 %0, {%1, %1};" : "=l"(r) : "f"(v));
    return r;
}

// ---------------------------------------------------------------------------
// Kernel A: 2 batch rows per block, f32x2-packed GEMV.
// Phases: load packed raw -> trend -> residual in place -> GEMV (1 FFMA2/iter)
// ---------------------------------------------------------------------------
__global__ void __launch_bounds__(256, 1) ka_encoder(
    const float* __restrict__ x,
    const float* __restrict__ Wt, const float* __restrict__ bt,
    const float* __restrict__ Ww, const float* __restrict__ bw,
    const float* __restrict__ Wdm, const float* __restrict__ bdm,
    const float* __restrict__ Wre, const float* __restrict__ bre)
{
    int b0 = blockIdx.x * 2;
    int tid = threadIdx.x;

    __shared__ __align__(16) ull sRaw[TLEN];   // packed (row0,row1); later residual
    __shared__ __align__(16) ull sT[TLEN];     // packed trend
    // overlay region reused after GEMV (sRaw is dead then)
    ull*   part = sRaw;                        // 256 ull
    float* sAcc = (float*)(sRaw + 256);        // 2*4*32 floats

    const float* xa = x + (size_t)b0 * TLEN * CH;
    const float* xb = xa + (size_t)TLEN * CH;
    for (int t = tid; t < TLEN; t += 256)
        sRaw[t] = pk(xa[(size_t)t * CH], xb[(size_t)t * CH]);
    __syncthreads();

    // trend: 7-tap mean with edge clamp
    for (int t = tid; t < TLEN; t += 256) {
        float sa = 0.f, sb = 0.f;
        #pragma unroll
        for (int d = -3; d <= 3; d++) {
            int u = t + d; u = min(max(u, 0), TLEN - 1);
            float2 q = unpk(sRaw[u]);
            sa += q.x; sb += q.y;
        }
        sT[t] = pk(sa / 7.0f, sb / 7.0f);
    }
    __syncthreads();

    // residual in place: sRaw[t] -= sT[t]  (element-own, safe)
    {
        const ull negone = pk1(-1.0f);
        for (int t = tid; t < TLEN; t += 256)
            sRaw[t] = fma2v(sT[t], negone, sRaw[t]);
    }
    __syncthreads();

    // GEMV: thread = (e, m, half); warp-uniform m
    int e = tid & 31;
    int m = (tid >> 5) & 3;      // 0: trend, 1..3: residual signals
    int half = tid >> 7;
    const float* W = (m == 0) ? Wt : (m == 1) ? Ww : (m == 2) ? Wdm : Wre;
    const ull* sig = (m == 0) ? sT : sRaw;
    int tb = half * (TLEN / 2);

    ull a0 = 0, a1 = 0, a2 = 0, a3 = 0;
    for (int t = tb; t < tb + TLEN / 2; t += 16) {
        float wv[16];
        #pragma unroll
        for (int u = 0; u < 16; u++) wv[u] = W[(t + u) * EDIM + e];
        #pragma unroll
        for (int u = 0; u < 16; u += 4) {
            a0 = fma2v(sig[t + u + 0], pk1(wv[u + 0]), a0);
            a1 = fma2v(sig[t + u + 1], pk1(wv[u + 1]), a1);
            a2 = fma2v(sig[t + u + 2], pk1(wv[u + 2]), a2);
            a3 = fma2v(sig[t + u + 3], pk1(wv[u + 3]), a3);
        }
    }
    ull mine = addx2(addx2(a0, a1), addx2(a2, a3));
    __syncthreads();                 // GEMV reads of sRaw/sT done before overlay
    part[tid] = mine;
    __syncthreads();
    if (tid < 128) {
        float2 q = unpk(addx2(part[tid], part[tid + 128]));
        const float* be = (m == 0) ? bt : (m == 1) ? bw : (m == 2) ? bdm : bre;
        float bias = be[e];
        sAcc[(0 * 4 + m) * EDIM + e] = tanhf(q.x + bias);
        sAcc[(1 * 4 + m) * EDIM + e] = tanhf(q.y + bias);
    }
    __syncthreads();
    if (tid < 64) {
        int r = tid >> 5, e2 = tid & 31;
        const float* a = sAcc + r * 4 * EDIM;
        g_v[(b0 + r) * EDIM + e2] =
            ((a[0 * EDIM + e2] + a[1 * EDIM + e2]) + a[2 * EDIM + e2]) + a[3 * EDIM + e2];
    }
}

// ---------------------------------------------------------------------------
// Kernel W (prep): M_h = Wo*Wh, M_g = Wo*Wg (stored transposed: [j][j']),
// Q = Wo*Wr, c_h = bdo*Wh, c_g = bdo*Wg, cvec = bdo*Wr.
// ---------------------------------------------------------------------------
__global__ void __launch_bounds__(128) kw_prep(
    const float* __restrict__ Wh, const float* __restrict__ Wg,
    const float* __restrict__ Wo, const float* __restrict__ bdo,
    const float* __restrict__ Wr)
{
    int j = blockIdx.x;     // 0..63
    int t = threadIdx.x;    // 0..127

    if (t < HDIM) {         // j' = t
        float mh = 0.f, mg = 0.f;
        #pragma unroll 8
        for (int e = 0; e < EDIM; e++) {
            float wo = Wo[t * EDIM + e];
            mh = fmaf(wo, Wh[e * HDIM + j], mh);
            mg = fmaf(wo, Wg[e * HDIM + j], mg);
        }
        g_Mh[j * HDIM + t] = mh;
        g_Mg[j * HDIM + t] = mg;
    }
    {
        float q = 0.f;
        #pragma unroll 8
        for (int e = 0; e < EDIM; e++)
            q = fmaf(Wo[j * EDIM + e], Wr[e * CH + t], q);
        g_Q[j * CH + t] = q;
    }
    if (j == 0) {
        float cv = 0.f;
        #pragma unroll 8
        for (int e = 0; e < EDIM; e++)
            cv = fmaf(bdo[e], Wr[e * CH + t], cv);
        g_cvec[t] = cv;
    }
    if (t == 0) {
        float chv = 0.f;
        for (int e = 0; e < EDIM; e++) chv = fmaf(bdo[e], Wh[e * HDIM + j], chv);
        g_ch[j] = chv;
    }
    if (t == 1) {
        float cgv = 0.f;
        for (int e = 0; e < EDIM; e++) cgv = fmaf(bdo[e], Wg[e * HDIM + j], cgv);
        g_cg[j] = cgv;
    }
}

// ---------------------------------------------------------------------------
// Kernel B: 336-step scan in (H,G)-space. 128 threads/row: thread (j = t>>1,
// h = t&1) tracks H_j,G_j (replicated per lane pair); each lane sums half the
// j'-range (16+16 FFMA2) and combines with one shfl_xor(1). One barrier/step,
// double-buffered u. Outputs running sums U_s (off critical path).
// ---------------------------------------------------------------------------
__global__ void __launch_bounds__(128) kb_scan(
    const float* __restrict__ Wh, const float* __restrict__ bh,
    const float* __restrict__ Wg, const float* __restrict__ bg)
{
    int b = blockIdx.x;
    int t = threadIdx.x;
    int j = t >> 1;
    int h = t & 1;

    __shared__ __align__(16) float sU[2][HDIM];

    // prologue: H_0 = v@Wh + bh, G_0 = v@Wg + bg
    float SH = bh[j], SG = bg[j];
    #pragma unroll 8
    for (int e = 0; e < EDIM; e++) {
        float ve = g_v[b * EDIM + e];
        SH = fmaf(ve, Wh[e * HDIM + j], SH);
        SG = fmaf(ve, Wg[e * HDIM + j], SG);
    }

    // M half-rows, packed pairs over j'
    ull Mh16[16], Mg16[16];
    {
        const float* mh = g_Mh + j * HDIM + h * 32;
        const float* mg = g_Mg + j * HDIM + h * 32;
        #pragma unroll
        for (int k = 0; k < 16; k++) {
            Mh16[k] = pk(mh[2 * k], mh[2 * k + 1]);
            Mg16[k] = pk(mg[2 * k], mg[2 * k + 1]);
        }
    }
    float chv = g_ch[j];
    float cgv = g_cg[j];
    float Uacc = 0.f;
    float* Uout = g_U + b * HDIM + j;
    int p = 0;
    __syncthreads();

    for (int s = 0; s < PRED; s++) {
        // activation from current state (replicated per lane pair)
        float sigH = __fdividef(1.0f, 1.0f + __expf(-SH));
        float sigG = __fdividef(1.0f, 1.0f + __expf(-SG));
        float u = (SH * sigH) * sigG;
        if (h == 0) sU[p][j] = u;
        __syncthreads();

        // half-range dot: j' in [32h, 32h+32)
        const float4* ub = ((const float4*)sU[p]) + h * 8;
        ull aH0 = 0, aH1 = 0, aG0 = 0, aG1 = 0;
        #pragma unroll
        for (int k = 0; k < 8; k++) {
            float4 f = ub[k];
            ull u0 = pk(f.x, f.y);
            ull u1 = pk(f.z, f.w);
            aH0 = fma2v(u0, Mh16[2 * k],     aH0);
            aH1 = fma2v(u1, Mh16[2 * k + 1], aH1);
            aG0 = fma2v(u0, Mg16[2 * k],     aG0);
            aG1 = fma2v(u1, Mg16[2 * k + 1], aG1);
        }
        float2 qh = unpk(addx2(aH0, aH1));
        float2 qg = unpk(addx2(aG0, aG1));
        float dH = qh.x + qh.y;
        float dG = qg.x + qg.y;
        dH += __shfl_xor_sync(0xffffffffu, dH, 1);
        dG += __shfl_xor_sync(0xffffffffu, dG, 1);
        SH += dH + chv;
        SG += dG + cgv;

        if (h == 0) {                      // off critical path
            Uacc += u;
            Uout[(size_t)s * (BATCH * HDIM)] = Uacc;
        }
        p ^= 1;
    }
}

// ---------------------------------------------------------------------------
// Kernel C: out[b,s,c] = (v_b@Wr + br)[c] + U[s,b,:]@Q[:,c] + (s+1)*cvec[c]
// Fully parallel GEMM over (b, s-chunks).
// ---------------------------------------------------------------------------
__global__ void __launch_bounds__(128) kc_project(
    const float* __restrict__ Wr, const float* __restrict__ br,
    float* __restrict__ out)
{
    int b = blockIdx.x;
    int chunk = blockIdx.y;
    int c = threadIdx.x;

    float base = br[c];
    #pragma unroll 8
    for (int e = 0; e < EDIM; e++)
        base = fmaf(g_v[b * EDIM + e], Wr[e * CH + c], base);
    float cv = g_cvec[c];

    ull qp[32];
    #pragma unroll
    for (int k = 0; k < 32; k++)
        qp[k] = pk(g_Q[(2 * k) * CH + c], g_Q[(2 * k + 1) * CH + c]);

    int sbeg = chunk * 56;
    for (int s = sbeg; s < sbeg + 56; s++) {
        const float4* up = (const float4*)(g_U + ((size_t)s * BATCH + b) * HDIM);
        ull a0 = 0, a1 = 0, a2 = 0, a3 = 0;
        #pragma unroll
        for (int k = 0; k < 16; k += 2) {
            float4 f0 = up[k];
            float4 f1 = up[k + 1];
            a0 = fma2v(pk(f0.x, f0.y), qp[2 * k],     a0);
            a1 = fma2v(pk(f0.z, f0.w), qp[2 * k + 1], a1);
            a2 = fma2v(pk(f1.x, f1.y), qp[2 * k + 2], a2);
            a3 = fma2v(pk(f1.z, f1.w), qp[2 * k + 3], a3);
        }
        float2 q = unpk(addx2(addx2(a0, a1), addx2(a2, a3)));
        float val = fmaf((float)(s + 1), cv, base + (q.x + q.y));
        out[((size_t)b * PRED + s) * CH + c] = val;
    }
}

// ---------------------------------------------------------------------------
extern "C" void kernel_launch(void* const* d_in, const int* in_sizes, int n_in,
                              void* d_out, int out_size)
{
    const float* x        = (const float*)d_in[0];
    const float* We_trend = (const float*)d_in[1];
    const float* be_trend = (const float*)d_in[2];
    const float* We_weekly= (const float*)d_in[3];
    const float* be_weekly= (const float*)d_in[4];
    const float* We_daily = (const float*)d_in[5];
    const float* be_daily = (const float*)d_in[6];
    const float* We_resid = (const float*)d_in[7];
    const float* be_resid = (const float*)d_in[8];
    const float* Wd_in    = (const float*)d_in[9];
    const float* bd_in    = (const float*)d_in[10];
    const float* Wd_gate  = (const float*)d_in[11];
    const float* bd_gate  = (const float*)d_in[12];
    const float* Wd_out   = (const float*)d_in[13];
    const float* bd_out   = (const float*)d_in[14];
    const float* Wr       = (const float*)d_in[15];
    const float* br       = (const float*)d_in[16];
    float* out = (float*)d_out;

    ka_encoder<<<BATCH / 2, 256>>>(x, We_trend, be_trend, We_weekly, be_weekly,
                                   We_daily, be_daily, We_resid, be_resid);
    kw_prep<<<HDIM, 128>>>(Wd_in, Wd_gate, Wd_out, bd_out, Wr);
    kb_scan<<<BATCH, 128>>>(Wd_in, bd_in, Wd_gate, bd_gate);
    kc_project<<<dim3(BATCH, 6), 128>>>(Wr, br, out);
}

// round 12
// speedup vs baseline: 1.3396x; 1.3396x over previous
#include <cuda_runtime.h>
#include <cuda_bf16.h>
#include <math.h>

#define BATCH 128
#define TLEN  2048
#define CH    128
#define EDIM  32
#define HDIM  64
#define PRED  336

typedef unsigned long long ull;

// scratch (allocation-free rule: __device__ globals)
__device__ __align__(16) float g_v[BATCH * EDIM];          // encoder output v
__device__ __align__(16) float g_U[PRED * BATCH * HDIM];   // running u-sums, 11 MB
__device__ __align__(16) float g_Mh[HDIM * HDIM];          // (Wo*Wh)^T rows
__device__ __align__(16) float g_Mg[HDIM * HDIM];
__device__ __align__(16) float g_ch[HDIM];
__device__ __align__(16) float g_cg[HDIM];
__device__ __align__(16) float g_Q [HDIM * CH];            // Wo*Wr
__device__ __align__(16) float g_cvec[CH];                 // bdo*Wr

// ---- packed f32x2 helpers (Blackwell) --------------------------------------
__device__ __forceinline__ ull fma2v(ull a, ull b, ull c) {
    ull d; asm("fma.rn.f32x2 %0, %1, %2, %3;" : "=l"(d) : "l"(a), "l"(b), "l"(c));
    return d;
}
__device__ __forceinline__ ull addx2(ull a, ull b) {
    ull d; asm("add.rn.f32x2 %0, %1, %2;" : "=l"(d) : "l"(a), "l"(b));
    return d;
}
__device__ __forceinline__ float2 unpk(ull v) {
    float2 r; asm("mov.b64 {%0, %1}, %2;" : "=f"(r.x), "=f"(r.y) : "l"(v));
    return r;
}
__device__ __forceinline__ ull pk(float lo, float hi) {
    ull v; asm("mov.b64 %0, {%1, %2};" : "=l"(v) : "f"(lo), "f"(hi));
    return v;
}
__device__ __forceinline__ ull pk1(float v) {
    ull r; asm("mov.b64 %0, {%1, %1};" : "=l"(r) : "f"(v));
    return r;
}

// ---------------------------------------------------------------------------
// Kernel A: 2 batch rows per block, f32x2-packed GEMV.
// ---------------------------------------------------------------------------
__global__ void __launch_bounds__(256, 1) ka_encoder(
    const float* __restrict__ x,
    const float* __restrict__ Wt, const float* __restrict__ bt,
    const float* __restrict__ Ww, const float* __restrict__ bw,
    const float* __restrict__ Wdm, const float* __restrict__ bdm,
    const float* __restrict__ Wre, const float* __restrict__ bre)
{
    int b0 = blockIdx.x * 2;
    int tid = threadIdx.x;

    __shared__ __align__(16) ull sRaw[TLEN];   // packed (row0,row1); later residual
    __shared__ __align__(16) ull sT[TLEN];     // packed trend
    ull*   part = sRaw;                        // overlay after GEMV
    float* sAcc = (float*)(sRaw + 256);

    const float* xa = x + (size_t)b0 * TLEN * CH;
    const float* xb = xa + (size_t)TLEN * CH;
    for (int t = tid; t < TLEN; t += 256)
        sRaw[t] = pk(xa[(size_t)t * CH], xb[(size_t)t * CH]);
    __syncthreads();

    for (int t = tid; t < TLEN; t += 256) {
        float sa = 0.f, sb = 0.f;
        #pragma unroll
        for (int d = -3; d <= 3; d++) {
            int u = t + d; u = min(max(u, 0), TLEN - 1);
            float2 q = unpk(sRaw[u]);
            sa += q.x; sb += q.y;
        }
        sT[t] = pk(sa / 7.0f, sb / 7.0f);
    }
    __syncthreads();

    {
        const ull negone = pk1(-1.0f);
        for (int t = tid; t < TLEN; t += 256)
            sRaw[t] = fma2v(sT[t], negone, sRaw[t]);
    }
    __syncthreads();

    int e = tid & 31;
    int m = (tid >> 5) & 3;      // 0: trend, 1..3: residual signals
    int half = tid >> 7;
    const float* W = (m == 0) ? Wt : (m == 1) ? Ww : (m == 2) ? Wdm : Wre;
    const ull* sig = (m == 0) ? sT : sRaw;
    int tb = half * (TLEN / 2);

    ull a0 = 0, a1 = 0, a2 = 0, a3 = 0;
    for (int t = tb; t < tb + TLEN / 2; t += 16) {
        float wv[16];
        #pragma unroll
        for (int u = 0; u < 16; u++) wv[u] = W[(t + u) * EDIM + e];
        #pragma unroll
        for (int u = 0; u < 16; u += 4) {
            a0 = fma2v(sig[t + u + 0], pk1(wv[u + 0]), a0);
            a1 = fma2v(sig[t + u + 1], pk1(wv[u + 1]), a1);
            a2 = fma2v(sig[t + u + 2], pk1(wv[u + 2]), a2);
            a3 = fma2v(sig[t + u + 3], pk1(wv[u + 3]), a3);
        }
    }
    ull mine = addx2(addx2(a0, a1), addx2(a2, a3));
    __syncthreads();
    part[tid] = mine;
    __syncthreads();
    if (tid < 128) {
        float2 q = unpk(addx2(part[tid], part[tid + 128]));
        const float* be = (m == 0) ? bt : (m == 1) ? bw : (m == 2) ? bdm : bre;
        float bias = be[e];
        sAcc[(0 * 4 + m) * EDIM + e] = tanhf(q.x + bias);
        sAcc[(1 * 4 + m) * EDIM + e] = tanhf(q.y + bias);
    }
    __syncthreads();
    if (tid < 64) {
        int r = tid >> 5, e2 = tid & 31;
        const float* a = sAcc + r * 4 * EDIM;
        g_v[(b0 + r) * EDIM + e2] =
            ((a[0 * EDIM + e2] + a[1 * EDIM + e2]) + a[2 * EDIM + e2]) + a[3 * EDIM + e2];
    }
}

// ---------------------------------------------------------------------------
// Kernel W (prep): M_h = Wo*Wh, M_g = Wo*Wg, Q = Wo*Wr, c-vectors.
// ---------------------------------------------------------------------------
__global__ void __launch_bounds__(128) kw_prep(
    const float* __restrict__ Wh, const float* __restrict__ Wg,
    const float* __restrict__ Wo, const float* __restrict__ bdo,
    const float* __restrict__ Wr)
{
    int j = blockIdx.x;     // 0..63
    int t = threadIdx.x;    // 0..127

    if (t < HDIM) {
        float mh = 0.f, mg = 0.f;
        #pragma unroll 8
        for (int e = 0; e < EDIM; e++) {
            float wo = Wo[t * EDIM + e];
            mh = fmaf(wo, Wh[e * HDIM + j], mh);
            mg = fmaf(wo, Wg[e * HDIM + j], mg);
        }
        g_Mh[j * HDIM + t] = mh;
        g_Mg[j * HDIM + t] = mg;
    }
    {
        float q = 0.f;
        #pragma unroll 8
        for (int e = 0; e < EDIM; e++)
            q = fmaf(Wo[j * EDIM + e], Wr[e * CH + t], q);
        g_Q[j * CH + t] = q;
    }
    if (j == 0) {
        float cv = 0.f;
        #pragma unroll 8
        for (int e = 0; e < EDIM; e++)
            cv = fmaf(bdo[e], Wr[e * CH + t], cv);
        g_cvec[t] = cv;
    }
    if (t == 0) {
        float chv = 0.f;
        for (int e = 0; e < EDIM; e++) chv = fmaf(bdo[e], Wh[e * HDIM + j], chv);
        g_ch[j] = chv;
    }
    if (t == 1) {
        float cgv = 0.f;
        for (int e = 0; e < EDIM; e++) cgv = fmaf(bdo[e], Wg[e * HDIM + j], cgv);
        g_cg[j] = cgv;
    }
}

// ---------------------------------------------------------------------------
// Kernel B: 336-step scan in (H,G)-space (hit prediction in R9; unchanged).
// ---------------------------------------------------------------------------
__global__ void __launch_bounds__(128) kb_scan(
    const float* __restrict__ Wh, const float* __restrict__ bh,
    const float* __restrict__ Wg, const float* __restrict__ bg)
{
    int b = blockIdx.x;
    int t = threadIdx.x;
    int j = t >> 1;
    int h = t & 1;

    __shared__ __align__(16) float sU[2][HDIM];

    float SH = bh[j], SG = bg[j];
    #pragma unroll 8
    for (int e = 0; e < EDIM; e++) {
        float ve = g_v[b * EDIM + e];
        SH = fmaf(ve, Wh[e * HDIM + j], SH);
        SG = fmaf(ve, Wg[e * HDIM + j], SG);
    }

    ull Mh16[16], Mg16[16];
    {
        const float* mh = g_Mh + j * HDIM + h * 32;
        const float* mg = g_Mg + j * HDIM + h * 32;
        #pragma unroll
        for (int k = 0; k < 16; k++) {
            Mh16[k] = pk(mh[2 * k], mh[2 * k + 1]);
            Mg16[k] = pk(mg[2 * k], mg[2 * k + 1]);
        }
    }
    float chv = g_ch[j];
    float cgv = g_cg[j];
    float Uacc = 0.f;
    float* Uout = g_U + b * HDIM + j;
    int p = 0;
    __syncthreads();

    for (int s = 0; s < PRED; s++) {
        float sigH = __fdividef(1.0f, 1.0f + __expf(-SH));
        float sigG = __fdividef(1.0f, 1.0f + __expf(-SG));
        float u = (SH * sigH) * sigG;
        if (h == 0) sU[p][j] = u;
        __syncthreads();

        const float4* ub = ((const float4*)sU[p]) + h * 8;
        ull aH0 = 0, aH1 = 0, aG0 = 0, aG1 = 0;
        #pragma unroll
        for (int k = 0; k < 8; k++) {
            float4 f = ub[k];
            ull u0 = pk(f.x, f.y);
            ull u1 = pk(f.z, f.w);
            aH0 = fma2v(u0, Mh16[2 * k],     aH0);
            aH1 = fma2v(u1, Mh16[2 * k + 1], aH1);
            aG0 = fma2v(u0, Mg16[2 * k],     aG0);
            aG1 = fma2v(u1, Mg16[2 * k + 1], aG1);
        }
        float2 qh = unpk(addx2(aH0, aH1));
        float2 qg = unpk(addx2(aG0, aG1));
        float dH = qh.x + qh.y;
        float dG = qg.x + qg.y;
        dH += __shfl_xor_sync(0xffffffffu, dH, 1);
        dG += __shfl_xor_sync(0xffffffffu, dG, 1);
        SH += dH + chv;
        SG += dG + cgv;

        if (h == 0) {
            Uacc += u;
            Uout[(size_t)s * (BATCH * HDIM)] = Uacc;
        }
        p ^= 1;
    }
}

// ---------------------------------------------------------------------------
// Kernel C: shared-tiled GEMM.
// out[b,s,c] = base[b,c] + U[s,b,:]@Q[:,c] + (s+1)*cvec[c]
// Block = (b, 112-step chunk); 256 threads; Q staged packed in shared once;
// 8-step sub-tiles with double-buffered U staging (prefetch into registers);
// thread computes 2s x 2c with 4 independent FFMA2 accumulators.
// ---------------------------------------------------------------------------
__global__ void __launch_bounds__(256) kc_project(
    const float* __restrict__ Wr, const float* __restrict__ br,
    float* __restrict__ out)
{
    int b = blockIdx.x;
    int chunk = blockIdx.y;          // 0..2
    int tid = threadIdx.x;
    int cp = tid & 63;               // channel pair: c = 2cp, 2cp+1
    int sg = tid >> 6;               // 0..3 -> steps 2sg, 2sg+1 in sub-tile

    __shared__ __align__(16) ull  sQ[HDIM * 64];        // 32 KB, [k*64 + cp]
    __shared__ __align__(16) float sUt[2][8 * 68];      // padded rows, dbl-buf
    __shared__ __align__(16) ull  sBase[64];

    for (int i = tid; i < HDIM * 64; i += 256) {
        int k = i >> 6, p = i & 63;
        sQ[i] = pk(g_Q[k * CH + 2 * p], g_Q[k * CH + 2 * p + 1]);
    }
    if (tid < 64) {
        float b0 = br[2 * tid], b1 = br[2 * tid + 1];
        #pragma unroll 8
        for (int e = 0; e < EDIM; e++) {
            float ve = g_v[b * EDIM + e];
            b0 = fmaf(ve, Wr[e * CH + 2 * tid],     b0);
            b1 = fmaf(ve, Wr[e * CH + 2 * tid + 1], b1);
        }
        sBase[tid] = pk(b0, b1);
    }

    int sbeg = chunk * 112;
    const float* Ubase = g_U + b * HDIM;
    // stage indices for this thread (2 elements of the 512-float sub-tile)
    int r0 = tid >> 6, k0 = tid & 63;          // rows 0..3
    int r1 = r0 + 4;                           // rows 4..7

    // prefetch sub-tile 0
    float f0 = Ubase[(size_t)(sbeg + r0) * (BATCH * HDIM) + k0];
    float f1 = Ubase[(size_t)(sbeg + r1) * (BATCH * HDIM) + k0];
    sUt[0][r0 * 68 + k0] = f0;
    sUt[0][r1 * 68 + k0] = f1;
    __syncthreads();

    ull basep = sBase[cp];
    ull cvp = pk(g_cvec[2 * cp], g_cvec[2 * cp + 1]);
    const ull* q0 = sQ + cp;

    for (int sub = 0; sub < 14; sub++) {
        int pb = sub & 1;
        // prefetch next sub-tile into registers (overlaps with compute)
        if (sub < 13) {
            int s0n = sbeg + (sub + 1) * 8;
            f0 = Ubase[(size_t)(s0n + r0) * (BATCH * HDIM) + k0];
            f1 = Ubase[(size_t)(s0n + r1) * (BATCH * HDIM) + k0];
        }

        const float* uA = sUt[pb] + (sg * 2) * 68;
        const float* uB = uA + 68;
        ull a0x = 0, a0y = 0, a1x = 0, a1y = 0;
        #pragma unroll
        for (int k = 0; k < HDIM; k += 8) {
            float4 A0 = *(const float4*)(uA + k);
            float4 B0 = *(const float4*)(uB + k);
            float4 A1 = *(const float4*)(uA + k + 4);
            float4 B1 = *(const float4*)(uB + k + 4);
            a0x = fma2v(pk1(A0.x), q0[(k + 0) * 64], a0x);
            a1x = fma2v(pk1(B0.x), q0[(k + 0) * 64], a1x);
            a0x = fma2v(pk1(A0.y), q0[(k + 1) * 64], a0x);
            a1x = fma2v(pk1(B0.y), q0[(k + 1) * 64], a1x);
            a0x = fma2v(pk1(A0.z), q0[(k + 2) * 64], a0x);
            a1x = fma2v(pk1(B0.z), q0[(k + 2) * 64], a1x);
            a0x = fma2v(pk1(A0.w), q0[(k + 3) * 64], a0x);
            a1x = fma2v(pk1(B0.w), q0[(k + 3) * 64], a1x);
            a0y = fma2v(pk1(A1.x), q0[(k + 4) * 64], a0y);
            a1y = fma2v(pk1(B1.x), q0[(k + 4) * 64], a1y);
            a0y = fma2v(pk1(A1.y), q0[(k + 5) * 64], a0y);
            a1y = fma2v(pk1(B1.y), q0[(k + 5) * 64], a1y);
            a0y = fma2v(pk1(A1.z), q0[(k + 6) * 64], a0y);
            a1y = fma2v(pk1(B1.z), q0[(k + 6) * 64], a1y);
            a0y = fma2v(pk1(A1.w), q0[(k + 7) * 64], a0y);
            a1y = fma2v(pk1(B1.w), q0[(k + 7) * 64], a1y);
        }
        int ssA = sbeg + sub * 8 + sg * 2;
        int ssB = ssA + 1;
        ull vA = fma2v(pk1((float)(ssA + 1)), cvp, addx2(basep, addx2(a0x, a0y)));
        ull vB = fma2v(pk1((float)(ssB + 1)), cvp, addx2(basep, addx2(a1x, a1y)));
        *(ull*)&out[((size_t)b * PRED + ssA) * CH + 2 * cp] = vA;
        *(ull*)&out[((size_t)b * PRED + ssB) * CH + 2 * cp] = vB;

        // commit prefetched data to the other buffer
        if (sub < 13) {
            int nb = pb ^ 1;
            sUt[nb][r0 * 68 + k0] = f0;
            sUt[nb][r1 * 68 + k0] = f1;
        }
        __syncthreads();
    }
}

// ---------------------------------------------------------------------------
extern "C" void kernel_launch(void* const* d_in, const int* in_sizes, int n_in,
                              void* d_out, int out_size)
{
    const float* x        = (const float*)d_in[0];
    const float* We_trend = (const float*)d_in[1];
    const float* be_trend = (const float*)d_in[2];
    const float* We_weekly= (const float*)d_in[3];
    const float* be_weekly= (const float*)d_in[4];
    const float* We_daily = (const float*)d_in[5];
    const float* be_daily = (const float*)d_in[6];
    const float* We_resid = (const float*)d_in[7];
    const float* be_resid = (const float*)d_in[8];
    const float* Wd_in    = (const float*)d_in[9];
    const float* bd_in    = (const float*)d_in[10];
    const float* Wd_gate  = (const float*)d_in[11];
    const float* bd_gate  = (const float*)d_in[12];
    const float* Wd_out   = (const float*)d_in[13];
    const float* bd_out   = (const float*)d_in[14];
    const float* Wr       = (const float*)d_in[15];
    const float* br       = (const float*)d_in[16];
    float* out = (float*)d_out;

    ka_encoder<<<BATCH / 2, 256>>>(x, We_trend, be_trend, We_weekly, be_weekly,
                                   We_daily, be_daily, We_resid, be_resid);
    kw_prep<<<HDIM, 128>>>(Wd_in, Wd_gate, Wd_out, bd_out, Wr);
    kb_scan<<<BATCH, 128>>>(Wd_in, bd_in, Wd_gate, bd_gate);
    kc_project<<<dim3(BATCH, 3), 256>>>(Wr, br, out);
}

// round 13
// speedup vs baseline: 1.6270x; 1.2146x over previous
#include <cuda_runtime.h>
#include <cuda_bf16.h>
#include <math.h>

#define BATCH 128
#define TLEN  2048
#define CH    128
#define EDIM  32
#define HDIM  64
#define PRED  336

typedef unsigned long long ull;

// scratch (allocation-free rule: __device__ globals)
__device__ __align__(16) float g_v[BATCH * EDIM];          // encoder output v
__device__ __align__(16) float g_Mh[HDIM * HDIM];          // (Wo*Wh)^T rows
__device__ __align__(16) float g_Mg[HDIM * HDIM];
__device__ __align__(16) float g_ch[HDIM];
__device__ __align__(16) float g_cg[HDIM];
__device__ __align__(16) float g_Qt[CH * HDIM];            // (Wo*Wr) transposed: [c][j]
__device__ __align__(16) float g_cvec[CH];                 // bdo*Wr

// ---- packed f32x2 helpers (Blackwell) --------------------------------------
__device__ __forceinline__ ull fma2v(ull a, ull b, ull c) {
    ull d; asm("fma.rn.f32x2 %0, %1, %2, %3;" : "=l"(d) : "l"(a), "l"(b), "l"(c));
    return d;
}
__device__ __forceinline__ ull addx2(ull a, ull b) {
    ull d; asm("add.rn.f32x2 %0, %1, %2;" : "=l"(d) : "l"(a), "l"(b));
    return d;
}
__device__ __forceinline__ float2 unpk(ull v) {
    float2 r; asm("mov.b64 {%0, %1}, %2;" : "=f"(r.x), "=f"(r.y) : "l"(v));
    return r;
}
__device__ __forceinline__ ull pk(float lo, float hi) {
    ull v; asm("mov.b64 %0, {%1, %2};" : "=l"(v) : "f"(lo), "f"(hi));
    return v;
}
__device__ __forceinline__ ull pk1(float v) {
    ull r; asm("mov.b64 %0, {%1, %1};" : "=l"(r) : "f"(v));
    return r;
}

// ---------------------------------------------------------------------------
// Kernel A: 2 batch rows per block, f32x2-packed GEMV (unchanged — on target).
// ---------------------------------------------------------------------------
__global__ void __launch_bounds__(256, 1) ka_encoder(
    const float* __restrict__ x,
    const float* __restrict__ Wt, const float* __restrict__ bt,
    const float* __restrict__ Ww, const float* __restrict__ bw,
    const float* __restrict__ Wdm, const float* __restrict__ bdm,
    const float* __restrict__ Wre, const float* __restrict__ bre)
{
    int b0 = blockIdx.x * 2;
    int tid = threadIdx.x;

    __shared__ __align__(16) ull sRaw[TLEN];   // packed (row0,row1); later residual
    __shared__ __align__(16) ull sT[TLEN];     // packed trend
    ull*   part = sRaw;                        // overlay after GEMV
    float* sAcc = (float*)(sRaw + 256);

    const float* xa = x + (size_t)b0 * TLEN * CH;
    const float* xb = xa + (size_t)TLEN * CH;
    for (int t = tid; t < TLEN; t += 256)
        sRaw[t] = pk(xa[(size_t)t * CH], xb[(size_t)t * CH]);
    __syncthreads();

    for (int t = tid; t < TLEN; t += 256) {
        float sa = 0.f, sb = 0.f;
        #pragma unroll
        for (int d = -3; d <= 3; d++) {
            int u = t + d; u = min(max(u, 0), TLEN - 1);
            float2 q = unpk(sRaw[u]);
            sa += q.x; sb += q.y;
        }
        sT[t] = pk(sa / 7.0f, sb / 7.0f);
    }
    __syncthreads();

    {
        const ull negone = pk1(-1.0f);
        for (int t = tid; t < TLEN; t += 256)
            sRaw[t] = fma2v(sT[t], negone, sRaw[t]);
    }
    __syncthreads();

    int e = tid & 31;
    int m = (tid >> 5) & 3;      // 0: trend, 1..3: residual signals
    int half = tid >> 7;
    const float* W = (m == 0) ? Wt : (m == 1) ? Ww : (m == 2) ? Wdm : Wre;
    const ull* sig = (m == 0) ? sT : sRaw;
    int tb = half * (TLEN / 2);

    ull a0 = 0, a1 = 0, a2 = 0, a3 = 0;
    for (int t = tb; t < tb + TLEN / 2; t += 16) {
        float wv[16];
        #pragma unroll
        for (int u = 0; u < 16; u++) wv[u] = W[(t + u) * EDIM + e];
        #pragma unroll
        for (int u = 0; u < 16; u += 4) {
            a0 = fma2v(sig[t + u + 0], pk1(wv[u + 0]), a0);
            a1 = fma2v(sig[t + u + 1], pk1(wv[u + 1]), a1);
            a2 = fma2v(sig[t + u + 2], pk1(wv[u + 2]), a2);
            a3 = fma2v(sig[t + u + 3], pk1(wv[u + 3]), a3);
        }
    }
    ull mine = addx2(addx2(a0, a1), addx2(a2, a3));
    __syncthreads();
    part[tid] = mine;
    __syncthreads();
    if (tid < 128) {
        float2 q = unpk(addx2(part[tid], part[tid + 128]));
        const float* be = (m == 0) ? bt : (m == 1) ? bw : (m == 2) ? bdm : bre;
        float bias = be[e];
        sAcc[(0 * 4 + m) * EDIM + e] = tanhf(q.x + bias);
        sAcc[(1 * 4 + m) * EDIM + e] = tanhf(q.y + bias);
    }
    __syncthreads();
    if (tid < 64) {
        int r = tid >> 5, e2 = tid & 31;
        const float* a = sAcc + r * 4 * EDIM;
        g_v[(b0 + r) * EDIM + e2] =
            ((a[0 * EDIM + e2] + a[1 * EDIM + e2]) + a[2 * EDIM + e2]) + a[3 * EDIM + e2];
    }
}

// ---------------------------------------------------------------------------
// Kernel W (prep): M_h = Wo*Wh, M_g = Wo*Wg, Qt = (Wo*Wr)^T, c-vectors.
// ---------------------------------------------------------------------------
__global__ void __launch_bounds__(128) kw_prep(
    const float* __restrict__ Wh, const float* __restrict__ Wg,
    const float* __restrict__ Wo, const float* __restrict__ bdo,
    const float* __restrict__ Wr)
{
    int j = blockIdx.x;     // 0..63
    int t = threadIdx.x;    // 0..127

    if (t < HDIM) {
        float mh = 0.f, mg = 0.f;
        #pragma unroll 8
        for (int e = 0; e < EDIM; e++) {
            float wo = Wo[t * EDIM + e];
            mh = fmaf(wo, Wh[e * HDIM + j], mh);
            mg = fmaf(wo, Wg[e * HDIM + j], mg);
        }
        g_Mh[j * HDIM + t] = mh;
        g_Mg[j * HDIM + t] = mg;
    }
    {
        float q = 0.f;
        #pragma unroll 8
        for (int e = 0; e < EDIM; e++)
            q = fmaf(Wo[j * EDIM + e], Wr[e * CH + t], q);
        g_Qt[t * HDIM + j] = q;                  // transposed: row per channel
    }
    if (j == 0) {
        float cv = 0.f;
        #pragma unroll 8
        for (int e = 0; e < EDIM; e++)
            cv = fmaf(bdo[e], Wr[e * CH + t], cv);
        g_cvec[t] = cv;
    }
    if (t == 0) {
        float chv = 0.f;
        for (int e = 0; e < EDIM; e++) chv = fmaf(bdo[e], Wh[e * HDIM + j], chv);
        g_ch[j] = chv;
    }
    if (t == 1) {
        float cgv = 0.f;
        for (int e = 0; e < EDIM; e++) cgv = fmaf(bdo[e], Wg[e * HDIM + j], cgv);
        g_cg[j] = cgv;
    }
}

// ---------------------------------------------------------------------------
// Kernel B (FUSED): 336-step scan in (H,G)-space + in-loop projection.
// Scan structure identical to R12 (latency path unchanged). Each thread also
// permanently owns channel c = t, with the Qt column in 32 packed registers;
// projection (32 FFMA2 + STG per step) fills the scan's stall bubbles.
// Double-buffered sU (step's u) and sUa (running sum) in shared.
// ---------------------------------------------------------------------------
__global__ void __launch_bounds__(128, 1) kb_scan(
    const float* __restrict__ Wh, const float* __restrict__ bh,
    const float* __restrict__ Wg, const float* __restrict__ bg,
    const float* __restrict__ Wr, const float* __restrict__ br,
    float* __restrict__ out)
{
    int b = blockIdx.x;
    int t = threadIdx.x;        // 128 threads
    int j = t >> 1;
    int h = t & 1;
    int c = t;                  // owned output channel

    __shared__ __align__(16) float sU[2][HDIM];
    __shared__ __align__(16) float sUa[2][HDIM];

    // prologue: H_0 = v@Wh + bh, G_0 = v@Wg + bg ; base_c = v@Wr + br
    float SH = bh[j], SG = bg[j];
    float basec = br[c];
    #pragma unroll 8
    for (int e = 0; e < EDIM; e++) {
        float ve = g_v[b * EDIM + e];
        SH = fmaf(ve, Wh[e * HDIM + j], SH);
        SG = fmaf(ve, Wg[e * HDIM + j], SG);
        basec = fmaf(ve, Wr[e * CH + c], basec);
    }

    // M half-rows (scan), packed pairs over j'
    ull Mh16[16], Mg16[16];
    {
        const float* mh = g_Mh + j * HDIM + h * 32;
        const float* mg = g_Mg + j * HDIM + h * 32;
        #pragma unroll
        for (int k = 0; k < 16; k++) {
            Mh16[k] = pk(mh[2 * k], mh[2 * k + 1]);
            Mg16[k] = pk(mg[2 * k], mg[2 * k + 1]);
        }
    }
    // Qt column for channel c (projection), packed pairs over j
    ull Qc[32];
    {
        const float4* qp = (const float4*)(g_Qt + c * HDIM);
        #pragma unroll
        for (int m = 0; m < 16; m++) {
            float4 f = qp[m];
            Qc[2 * m]     = pk(f.x, f.y);
            Qc[2 * m + 1] = pk(f.z, f.w);
        }
    }
    float chv = g_ch[j];
    float cgv = g_cg[j];
    float cvc = g_cvec[c];
    float Uacc = 0.f;
    float* outb = out + (size_t)b * PRED * CH + c;
    int p = 0;
    __syncthreads();

    for (int s = 0; s < PRED; s++) {
        // activation from current state (replicated per lane pair)
        float sigH = __fdividef(1.0f, 1.0f + __expf(-SH));
        float sigG = __fdividef(1.0f, 1.0f + __expf(-SG));
        float u = (SH * sigH) * sigG;
        if (h == 0) {
            Uacc += u;
            sU[p][j]  = u;
            sUa[p][j] = Uacc;
        }
        __syncthreads();

        // ---- scan dot: half-range j' in [32h, 32h+32) ----
        const float4* ub = ((const float4*)sU[p]) + h * 8;
        ull aH0 = 0, aH1 = 0, aG0 = 0, aG1 = 0;
        #pragma unroll
        for (int k = 0; k < 8; k++) {
            float4 f = ub[k];
            ull u0 = pk(f.x, f.y);
            ull u1 = pk(f.z, f.w);
            aH0 = fma2v(u0, Mh16[2 * k],     aH0);
            aH1 = fma2v(u1, Mh16[2 * k + 1], aH1);
            aG0 = fma2v(u0, Mg16[2 * k],     aG0);
            aG1 = fma2v(u1, Mg16[2 * k + 1], aG1);
        }
        float2 qh = unpk(addx2(aH0, aH1));
        float2 qg = unpk(addx2(aG0, aG1));
        float dH = qh.x + qh.y;
        float dG = qg.x + qg.y;
        dH += __shfl_xor_sync(0xffffffffu, dH, 1);
        dG += __shfl_xor_sync(0xffffffffu, dG, 1);
        SH += dH + chv;
        SG += dG + cgv;

        // ---- projection (off critical path): out[b,s,c] ----
        {
            const float4* ua = (const float4*)sUa[p];
            ull a0 = 0, a1 = 0, a2 = 0, a3 = 0;
            #pragma unroll
            for (int m = 0; m < 16; m += 2) {
                float4 f0 = ua[m];
                float4 f1 = ua[m + 1];
                a0 = fma2v(pk(f0.x, f0.y), Qc[2 * m],     a0);
                a1 = fma2v(pk(f0.z, f0.w), Qc[2 * m + 1], a1);
                a2 = fma2v(pk(f1.x, f1.y), Qc[2 * m + 2], a2);
                a3 = fma2v(pk(f1.z, f1.w), Qc[2 * m + 3], a3);
            }
            float2 q = unpk(addx2(addx2(a0, a1), addx2(a2, a3)));
            outb[(size_t)s * CH] = fmaf((float)(s + 1), cvc, basec + (q.x + q.y));
        }
        p ^= 1;
    }
}

// ---------------------------------------------------------------------------
extern "C" void kernel_launch(void* const* d_in, const int* in_sizes, int n_in,
                              void* d_out, int out_size)
{
    const float* x        = (const float*)d_in[0];
    const float* We_trend = (const float*)d_in[1];
    const float* be_trend = (const float*)d_in[2];
    const float* We_weekly= (const float*)d_in[3];
    const float* be_weekly= (const float*)d_in[4];
    const float* We_daily = (const float*)d_in[5];
    const float* be_daily = (const float*)d_in[6];
    const float* We_resid = (const float*)d_in[7];
    const float* be_resid = (const float*)d_in[8];
    const float* Wd_in    = (const float*)d_in[9];
    const float* bd_in    = (const float*)d_in[10];
    const float* Wd_gate  = (const float*)d_in[11];
    const float* bd_gate  = (const float*)d_in[12];
    const float* Wd_out   = (const float*)d_in[13];
    const float* bd_out   = (const float*)d_in[14];
    const float* Wr       = (const float*)d_in[15];
    const float* br       = (const float*)d_in[16];
    float* out = (float*)d_out;

    ka_encoder<<<BATCH / 2, 256>>>(x, We_trend, be_trend, We_weekly, be_weekly,
                                   We_daily, be_daily, We_resid, be_resid);
    kw_prep<<<HDIM, 128>>>(Wd_in, Wd_gate, Wd_out, bd_out, Wr);
    kb_scan<<<BATCH, 128>>>(Wd_in, bd_in, Wd_gate, bd_gate, Wr, br, out);
}